// round 4
// baseline (speedup 1.0000x reference)
#include <cuda_runtime.h>

#define B 8
#define N 2048
#define BN (B * N)
#define DELTA 1e-7f

#define TPB 512
#define CROWS 4                         // rows per chunk
#define CHUNK_FLOATS (CROWS * N)        // 8192 floats = 32KB
#define NCHUNKS (N / CROWS)             // 512 chunks per batch
#define CTAS_PER_B 36
#define GRID (B * CTAS_PER_B)           // 288 CTAs (2 per SM)
#define STAGES 3
#define MAXCH ((NCHUNKS + CTAS_PER_B - 1) / CTAS_PER_B)   // 15

// Persistent scratch (__device__ globals per allocation rules).
__device__ float  g_odout1[BN];
__device__ float  g_odout2[BN];
__device__ float  g_pop1[BN];
__device__ float4 g_sir6[BN * 2];   // SIR after iter 0 (6 floats in 2x float4)
__device__ float  g_colA[BN * 4];   // iter0 colsums [OD_in, SIR_in*3] (zeroed by pass2)
__device__ float  g_colB[BN * 8];   // iter1 colsums [OD_in, SIR_in*6, pad] (zeroed by final)

__device__ __forceinline__ float dnn(float n, float d) { return (d == 0.0f) ? 0.0f : n / d; }

__device__ __forceinline__ void cp_async16(float* s, const float* g) {
    unsigned sa = (unsigned)__cvta_generic_to_shared(s);
    asm volatile("cp.async.cg.shared.global [%0], [%1], 16;" :: "r"(sa), "l"(g));
}
__device__ __forceinline__ void cp_commit() { asm volatile("cp.async.commit_group;"); }
template<int Nw> __device__ __forceinline__ void cp_wait() {
    asm volatile("cp.async.wait_group %0;" :: "n"(Nw));
}

__device__ __forceinline__ void load_chunk(float* dst, const float* src, int tid) {
#pragma unroll
    for (int v = 0; v < CHUNK_FLOATS / 4 / TPB; v++)   // 4 x 16B per thread
        cp_async16(dst + (size_t)(tid + v * TPB) * 4, src + (size_t)(tid + v * TPB) * 4);
}

// Row-sum partials: warp w handles quarter (w&3) of row (w>>2). All 16 warps busy.
__device__ __forceinline__ void rowsum_partials(const float* buf, float* s_part,
                                                int warp, int lane) {
    const int r = warp >> 2, q = warp & 3;
    const float4* row = reinterpret_cast<const float4*>(buf + r * N) + q * 128 + lane;
    float s = 0.0f;
#pragma unroll
    for (int t = 0; t < 4; t++) {
        float4 v = row[t * 32];
        s += (v.x + v.y) + (v.z + v.w);
    }
#pragma unroll
    for (int o = 16; o; o >>= 1) s += __shfl_xor_sync(0xffffffffu, s, o);
    if (lane == 0) s_part[r * 4 + q] = s;
}

// ---------------------------------------------------------------------------
// Pass 1 (iteration 0, K=4). Phase-pipelined: rowsum(c) || FMA(c-1).
// ---------------------------------------------------------------------------
__global__ void __launch_bounds__(TPB, 2) pass1_kernel(
    const float* __restrict__ inp, const float* __restrict__ od_all)
{
    extern __shared__ float sm[];
    float*  bufs   = sm;                                    // [3][8192]
    float*  s_part = sm + STAGES * CHUNK_FLOATS;            // [CROWS*4]
    float4* s_w    = reinterpret_cast<float4*>(s_part + CROWS * 4); // [2][CROWS]
    float4* s_st   = s_w + 2 * CROWS;                       // [MAXCH*CROWS]

    const int b    = blockIdx.x / CTAS_PER_B;
    const int slot = blockIdx.x % CTAS_PER_B;
    const int tid  = threadIdx.x;
    const int warp = tid >> 5, lane = tid & 31;
    const float* OD = od_all + (size_t)(b * 2) * N * N;
    const int nch = (NCHUNKS - 1 - slot) / CTAS_PER_B + 1;

    // One-time prefetch of per-row input features
    for (int L = tid; L < nch * CROWS; L += TPB) {
        int i = (slot + (L / CROWS) * CTAS_PER_B) * CROWS + (L & (CROWS - 1));
        s_st[L] = reinterpret_cast<const float4*>(inp)[b * N + i];
    }

#pragma unroll
    for (int s = 0; s < 2; s++) {
        load_chunk(bufs + s * CHUNK_FLOATS,
                   OD + (size_t)(slot + s * CTAS_PER_B) * CROWS * N, tid);
        cp_commit();
    }

    float acc[4][4] = {};
    for (int c = 0; c <= nch; c++) {
        if (c < nch) cp_wait<1>();
        __syncthreads();                                 // barrier1

        if (c < nch)
            rowsum_partials(bufs + (c % STAGES) * CHUNK_FLOATS, s_part, warp, lane);

        if (c > 0) {
            const float4* colp =
                reinterpret_cast<const float4*>(bufs + ((c - 1) % STAGES) * CHUNK_FLOATS) + tid;
            const float4* wrow = &s_w[((c - 1) & 1) * CROWS];
#pragma unroll
            for (int r = 0; r < CROWS; r++) {
                float4 v = colp[r * (N / 4)];
                float4 w = wrow[r];
                float wk[4] = {w.x, w.y, w.z, w.w};
#pragma unroll
                for (int k = 0; k < 4; k++) {
                    acc[0][k] = fmaf(v.x, wk[k], acc[0][k]);
                    acc[1][k] = fmaf(v.y, wk[k], acc[1][k]);
                    acc[2][k] = fmaf(v.z, wk[k], acc[2][k]);
                    acc[3][k] = fmaf(v.w, wk[k], acc[3][k]);
                }
            }
        }
        __syncthreads();                                 // barrier2

        if (c < nch && tid < CROWS) {                    // combine -> weights(c)
            float s = s_part[tid * 4 + 0] + s_part[tid * 4 + 1] +
                      s_part[tid * 4 + 2] + s_part[tid * 4 + 3];
            float4 f = s_st[c * CROWS + tid];
            int gi = b * N + (slot + c * CTAS_PER_B) * CROWS + tid;
            float ratio = dnn(f.x, DELTA + s);
            float sc = ratio < 1.0f ? ratio : 1.0f;
            g_odout1[gi] = sc * s;
            float dp = DELTA + f.x;
            s_w[(c & 1) * CROWS + tid] =
                make_float4(sc, sc * dnn(f.y, dp), sc * dnn(f.z, dp), sc * dnn(f.w, dp));
        }

        if (c + 2 < nch)
            load_chunk(bufs + ((c + 2) % STAGES) * CHUNK_FLOATS,
                       OD + (size_t)(slot + (c + 2) * CTAS_PER_B) * CROWS * N, tid);
        cp_commit();
    }

#pragma unroll
    for (int cc = 0; cc < 4; cc++) {
        float* dst = g_colA + ((size_t)b * N + tid * 4 + cc) * 4;
#pragma unroll
        for (int k = 0; k < 4; k++) atomicAdd(dst + k, acc[cc][k]);
    }
}

// ---------------------------------------------------------------------------
// Pass 2 (iteration 1, K=7). Fuses update<3> into the state prefetch.
// ---------------------------------------------------------------------------
__global__ void __launch_bounds__(TPB, 2) pass2_kernel(
    const float* __restrict__ inp, const float* __restrict__ od_all)
{
    extern __shared__ float sm[];
    float*  bufs   = sm;                                    // [3][8192]
    float*  s_part = sm + STAGES * CHUNK_FLOATS;            // [CROWS*4]
    float4* s_w    = reinterpret_cast<float4*>(s_part + CROWS * 4); // [2][CROWS][2]
    float4* s_st   = s_w + 2 * CROWS * 2;                   // [MAXCH*CROWS*2]

    const int b    = blockIdx.x / CTAS_PER_B;
    const int slot = blockIdx.x % CTAS_PER_B;
    const int tid  = threadIdx.x;
    const int warp = tid >> 5, lane = tid & 31;
    const float* OD = od_all + (size_t)(b * 2 + 1) * N * N;
    const int nch = (NCHUNKS - 1 - slot) / CTAS_PER_B + 1;

    // One-time prefetch + fused iter-0 state update; re-zero colA for replay
    for (int L = tid; L < nch * CROWS; L += TPB) {
        int i  = (slot + (L / CROWS) * CTAS_PER_B) * CROWS + (L & (CROWS - 1));
        int gi = b * N + i;
        float4 f   = reinterpret_cast<const float4*>(inp)[gi];
        float4 csA = reinterpret_cast<float4*>(g_colA)[gi];
        reinterpret_cast<float4*>(g_colA)[gi] = make_float4(0, 0, 0, 0);
        float od1 = g_odout1[gi];
        float dp0 = DELTA + f.x;
        float s60 = f.y - od1 * dnn(f.y, dp0);
        float s61 = f.z - od1 * dnn(f.z, dp0);
        float s62 = f.w - od1 * dnn(f.w, dp0);
        float pop1 = f.x - od1 + csA.x;
        s_st[L * 2 + 0] = make_float4(pop1, s60, s61, s62);
        s_st[L * 2 + 1] = make_float4(csA.y, csA.z, csA.w, 0.0f);
        g_pop1[gi] = pop1;
        g_sir6[gi * 2 + 0] = make_float4(s60, s61, s62, csA.y);
        g_sir6[gi * 2 + 1] = make_float4(csA.z, csA.w, 0.0f, 0.0f);
    }

#pragma unroll
    for (int s = 0; s < 2; s++) {
        load_chunk(bufs + s * CHUNK_FLOATS,
                   OD + (size_t)(slot + s * CTAS_PER_B) * CROWS * N, tid);
        cp_commit();
    }

    float acc[4][7] = {};
    for (int c = 0; c <= nch; c++) {
        if (c < nch) cp_wait<1>();
        __syncthreads();                                 // barrier1

        if (c < nch)
            rowsum_partials(bufs + (c % STAGES) * CHUNK_FLOATS, s_part, warp, lane);

        if (c > 0) {
            const float4* colp =
                reinterpret_cast<const float4*>(bufs + ((c - 1) % STAGES) * CHUNK_FLOATS) + tid;
            const float4* wrow = &s_w[((c - 1) & 1) * CROWS * 2];
#pragma unroll
            for (int r = 0; r < CROWS; r++) {
                float4 v  = colp[r * (N / 4)];
                float4 wa = wrow[r * 2 + 0];
                float4 wb = wrow[r * 2 + 1];
                float wk[7] = {wa.x, wa.y, wa.z, wa.w, wb.x, wb.y, wb.z};
#pragma unroll
                for (int k = 0; k < 7; k++) {
                    acc[0][k] = fmaf(v.x, wk[k], acc[0][k]);
                    acc[1][k] = fmaf(v.y, wk[k], acc[1][k]);
                    acc[2][k] = fmaf(v.z, wk[k], acc[2][k]);
                    acc[3][k] = fmaf(v.w, wk[k], acc[3][k]);
                }
            }
        }
        __syncthreads();                                 // barrier2

        if (c < nch && tid < CROWS) {
            float s = s_part[tid * 4 + 0] + s_part[tid * 4 + 1] +
                      s_part[tid * 4 + 2] + s_part[tid * 4 + 3];
            float4 a  = s_st[(c * CROWS + tid) * 2 + 0];   // pop1, s6[0..2]
            float4 bb = s_st[(c * CROWS + tid) * 2 + 1];   // s6[3..5]
            int gi = b * N + (slot + c * CTAS_PER_B) * CROWS + tid;
            float ratio = dnn(a.x, DELTA + s);
            float sc = ratio < 1.0f ? ratio : 1.0f;
            g_odout2[gi] = sc * s;
            float dp1 = DELTA + a.x;
            s_w[((c & 1) * CROWS + tid) * 2 + 0] =
                make_float4(sc, sc * dnn(a.y, dp1), sc * dnn(a.z, dp1), sc * dnn(a.w, dp1));
            s_w[((c & 1) * CROWS + tid) * 2 + 1] =
                make_float4(sc * dnn(bb.x, dp1), sc * dnn(bb.y, dp1),
                            sc * dnn(bb.z, dp1), 0.0f);
        }

        if (c + 2 < nch)
            load_chunk(bufs + ((c + 2) % STAGES) * CHUNK_FLOATS,
                       OD + (size_t)(slot + (c + 2) * CTAS_PER_B) * CROWS * N, tid);
        cp_commit();
    }

#pragma unroll
    for (int cc = 0; cc < 4; cc++) {
        float* dst = g_colB + ((size_t)b * N + tid * 4 + cc) * 8;
#pragma unroll
        for (int k = 0; k < 7; k++) atomicAdd(dst + k, acc[cc][k]);
    }
}

// ---------------------------------------------------------------------------
// Final: fuses update<6> + GEMM(12->64) + relu + concat(pop). Re-zeros colB.
// ---------------------------------------------------------------------------
__global__ void __launch_bounds__(256) final_kernel(
    const float* __restrict__ kern,
    const float* __restrict__ bias,
    float* __restrict__ out)
{
    __shared__ float s_kern[12 * 64];
    const int tid = threadIdx.x;
    for (int t = tid; t < 12 * 64; t += 256) s_kern[t] = kern[t];
    __syncthreads();

    const int rowl = tid >> 6;
    const int c    = tid & 63;
    const int gi   = blockIdx.x * 4 + rowl;

    float pop1   = g_pop1[gi];
    float odout2 = g_odout2[gi];
    float4 a   = g_sir6[gi * 2 + 0];
    float4 b4  = g_sir6[gi * 2 + 1];
    float4 cb0 = reinterpret_cast<const float4*>(g_colB)[gi * 2 + 0];
    float4 cb1 = reinterpret_cast<const float4*>(g_colB)[gi * 2 + 1];

    float dp1 = DELTA + pop1;
    float s12[12];
    s12[0] = a.x  - odout2 * dnn(a.x,  dp1);
    s12[1] = a.y  - odout2 * dnn(a.y,  dp1);
    s12[2] = a.z  - odout2 * dnn(a.z,  dp1);
    s12[3] = a.w  - odout2 * dnn(a.w,  dp1);
    s12[4] = b4.x - odout2 * dnn(b4.x, dp1);
    s12[5] = b4.y - odout2 * dnn(b4.y, dp1);
    s12[6]  = cb0.y; s12[7]  = cb0.z; s12[8]  = cb0.w;
    s12[9]  = cb1.x; s12[10] = cb1.y; s12[11] = cb1.z;

    float acc = __ldg(&bias[c]);
#pragma unroll
    for (int f = 0; f < 12; f++)
        acc = fmaf(s12[f], s_kern[f * 64 + c], acc);
    acc = fmaxf(acc, 0.0f);

    float* orow = out + (size_t)gi * 65;
    orow[1 + c] = acc;
    if (c == 0) orow[0] = pop1 - odout2 + cb0.x;

    __syncthreads();                  // all colB reads done before re-zero
    if (c < 8) g_colB[gi * 8 + c] = 0.0f;
}

// ---------------------------------------------------------------------------
extern "C" void kernel_launch(void* const* d_in, const int* in_sizes, int n_in,
                              void* d_out, int out_size) {
    const float* inp  = (const float*)d_in[0];  // input_feature (8,2048,4)
    const float* od   = (const float*)d_in[1];  // OD_all (8,2,2048,2048)
    const float* kern = (const float*)d_in[2];  // kernel (12,64)
    const float* bias = (const float*)d_in[3];  // bias (64)
    float* out = (float*)d_out;                 // (8,2048,65)

    const int SMEM1 = STAGES * CHUNK_FLOATS * 4 + CROWS * 4 * 4
                    + 2 * CROWS * 16 + MAXCH * CROWS * 16;
    const int SMEM2 = STAGES * CHUNK_FLOATS * 4 + CROWS * 4 * 4
                    + 2 * CROWS * 2 * 16 + MAXCH * CROWS * 32;

    cudaFuncSetAttribute(pass1_kernel, cudaFuncAttributeMaxDynamicSharedMemorySize, SMEM1);
    cudaFuncSetAttribute(pass2_kernel, cudaFuncAttributeMaxDynamicSharedMemorySize, SMEM2);

    pass1_kernel<<<GRID, TPB, SMEM1>>>(inp, od);
    pass2_kernel<<<GRID, TPB, SMEM2>>>(inp, od);
    final_kernel<<<BN / 4, 256>>>(kern, bias, out);
}

// round 5
// speedup vs baseline: 1.2424x; 1.2424x over previous
#include <cuda_runtime.h>

#define B 8
#define N 2048
#define BN (B * N)
#define DELTA 1e-7f

#define TPB 512
#define CROWS 8                         // rows per chunk: 8*2048*4B = 64KB
#define CHUNK_FLOATS (CROWS * N)        // 16384 floats
#define NCHUNKS (N / CROWS)             // 256 chunks per batch
#define CTAS_PER_B 18
#define GRID (B * CTAS_PER_B)           // 144 CTAs (1 per SM)
#define STAGES 3
#define MAXCH ((NCHUNKS + CTAS_PER_B - 1) / CTAS_PER_B)   // 15

// Persistent scratch (__device__ globals per allocation rules).
__device__ float  g_odout1[BN];
__device__ float  g_odout2[BN];
__device__ float  g_pop1[BN];
__device__ float4 g_sir6[BN * 2];   // SIR after iter 0 (6 floats in 2x float4)
__device__ float  g_colA[BN * 4];   // iter0 colsums [OD_in, SIR_in*3] (zeroed by pass2)
__device__ float  g_colB[BN * 8];   // iter1 colsums [OD_in, SIR_in*6, pad] (zeroed by final)

__device__ __forceinline__ float dnn(float n, float d) { return (d == 0.0f) ? 0.0f : n / d; }

__device__ __forceinline__ void cp_async16(float* s, const float* g) {
    unsigned sa = (unsigned)__cvta_generic_to_shared(s);
    asm volatile("cp.async.cg.shared.global [%0], [%1], 16;" :: "r"(sa), "l"(g));
}
__device__ __forceinline__ void cp_commit() { asm volatile("cp.async.commit_group;"); }
template<int Nw> __device__ __forceinline__ void cp_wait() {
    asm volatile("cp.async.wait_group %0;" :: "n"(Nw));
}

__device__ __forceinline__ void load_chunk(float* dst, const float* src, int tid) {
#pragma unroll
    for (int v = 0; v < CHUNK_FLOATS / 4 / TPB; v++)   // 8 x 16B per thread
        cp_async16(dst + (size_t)(tid + v * TPB) * 4, src + (size_t)(tid + v * TPB) * 4);
}

// Row-sum partials: 2 warps per row (warp w -> row w>>1, half w&1).
// All 16 warps busy; each lane reads 8 float4.
__device__ __forceinline__ void rowsum_partials(const float* buf, float* s_part,
                                                int warp, int lane) {
    const int r = warp >> 1, q = warp & 1;
    const float4* row = reinterpret_cast<const float4*>(buf + r * N) + q * 256 + lane;
    float s = 0.0f;
#pragma unroll
    for (int t = 0; t < 8; t++) {
        float4 v = row[t * 32];
        s += (v.x + v.y) + (v.z + v.w);
    }
#pragma unroll
    for (int o = 16; o; o >>= 1) s += __shfl_xor_sync(0xffffffffu, s, o);
    if (lane == 0) s_part[r * 2 + q] = s;
}

// ---------------------------------------------------------------------------
// Pass 1 (iteration 0, K=4). Phase-pipelined: rowsum(c) || FMA(c-1), 64KB chunks.
// ---------------------------------------------------------------------------
__global__ void __launch_bounds__(TPB, 1) pass1_kernel(
    const float* __restrict__ inp, const float* __restrict__ od_all)
{
    extern __shared__ float sm[];
    float*  bufs   = sm;                                             // [3][16384]
    float*  s_part = sm + STAGES * CHUNK_FLOATS;                     // [CROWS*2]
    float4* s_w    = reinterpret_cast<float4*>(s_part + CROWS * 2);  // [2][CROWS]
    float4* s_st   = s_w + 2 * CROWS;                                // [MAXCH*CROWS]

    const int b    = blockIdx.x / CTAS_PER_B;
    const int slot = blockIdx.x % CTAS_PER_B;
    const int tid  = threadIdx.x;
    const int warp = tid >> 5, lane = tid & 31;
    const float* OD = od_all + (size_t)(b * 2) * N * N;
    const int nch = (NCHUNKS - 1 - slot) / CTAS_PER_B + 1;   // 14 or 15

    // One-time prefetch of per-row input features
    for (int L = tid; L < nch * CROWS; L += TPB) {
        int i = (slot + (L >> 3) * CTAS_PER_B) * CROWS + (L & 7);
        s_st[L] = reinterpret_cast<const float4*>(inp)[b * N + i];
    }

#pragma unroll
    for (int s = 0; s < 2; s++) {
        load_chunk(bufs + s * CHUNK_FLOATS,
                   OD + (size_t)(slot + s * CTAS_PER_B) * CROWS * N, tid);
        cp_commit();
    }

    float acc[4][4] = {};
    for (int c = 0; c <= nch; c++) {
        if (c < nch) cp_wait<1>();
        __syncthreads();                                 // barrier1

        // Same interval: rowsum partials of chunk c, FMA over chunk c-1.
        if (c < nch)
            rowsum_partials(bufs + (c % STAGES) * CHUNK_FLOATS, s_part, warp, lane);

        if (c > 0) {
            const float4* colp =
                reinterpret_cast<const float4*>(bufs + ((c - 1) % STAGES) * CHUNK_FLOATS) + tid;
            const float4* wrow = &s_w[((c - 1) & 1) * CROWS];
#pragma unroll
            for (int r = 0; r < CROWS; r++) {
                float4 v = colp[r * (N / 4)];
                float4 w = wrow[r];
                float wk[4] = {w.x, w.y, w.z, w.w};
#pragma unroll
                for (int k = 0; k < 4; k++) {
                    acc[0][k] = fmaf(v.x, wk[k], acc[0][k]);
                    acc[1][k] = fmaf(v.y, wk[k], acc[1][k]);
                    acc[2][k] = fmaf(v.z, wk[k], acc[2][k]);
                    acc[3][k] = fmaf(v.w, wk[k], acc[3][k]);
                }
            }
        }
        __syncthreads();                                 // barrier2

        if (c < nch && tid < CROWS) {                    // combine -> weights(c)
            float s = s_part[tid * 2 + 0] + s_part[tid * 2 + 1];
            float4 f = s_st[c * CROWS + tid];
            int gi = b * N + (slot + c * CTAS_PER_B) * CROWS + tid;
            float ratio = dnn(f.x, DELTA + s);
            float sc = ratio < 1.0f ? ratio : 1.0f;
            g_odout1[gi] = sc * s;
            float dp = DELTA + f.x;
            s_w[(c & 1) * CROWS + tid] =
                make_float4(sc, sc * dnn(f.y, dp), sc * dnn(f.z, dp), sc * dnn(f.w, dp));
        }

        // Load chunk c+2 into buffer (c+2)%3 == (c-1)%3 (FMA on c-1 done above).
        if (c + 2 < nch)
            load_chunk(bufs + ((c + 2) % STAGES) * CHUNK_FLOATS,
                       OD + (size_t)(slot + (c + 2) * CTAS_PER_B) * CROWS * N, tid);
        cp_commit();       // exactly one group per iteration keeps wait<1> aligned
    }

    // Single flush per CTA
#pragma unroll
    for (int cc = 0; cc < 4; cc++) {
        float* dst = g_colA + ((size_t)b * N + tid * 4 + cc) * 4;
#pragma unroll
        for (int k = 0; k < 4; k++) atomicAdd(dst + k, acc[cc][k]);
    }
}

// ---------------------------------------------------------------------------
// Pass 2 (iteration 1, K=7). Fuses update<3> in the state prefetch.
// ---------------------------------------------------------------------------
__global__ void __launch_bounds__(TPB, 1) pass2_kernel(
    const float* __restrict__ inp, const float* __restrict__ od_all)
{
    extern __shared__ float sm[];
    float*  bufs   = sm;                                             // [3][16384]
    float*  s_part = sm + STAGES * CHUNK_FLOATS;                     // [CROWS*2]
    float4* s_w    = reinterpret_cast<float4*>(s_part + CROWS * 2);  // [2][CROWS][2]
    float4* s_st   = s_w + 2 * CROWS * 2;                            // [MAXCH*CROWS*2]

    const int b    = blockIdx.x / CTAS_PER_B;
    const int slot = blockIdx.x % CTAS_PER_B;
    const int tid  = threadIdx.x;
    const int warp = tid >> 5, lane = tid & 31;
    const float* OD = od_all + (size_t)(b * 2 + 1) * N * N;
    const int nch = (NCHUNKS - 1 - slot) / CTAS_PER_B + 1;

    // One-time prefetch + fused iter-0 state update; re-zero colA for replay
    for (int L = tid; L < nch * CROWS; L += TPB) {
        int i  = (slot + (L >> 3) * CTAS_PER_B) * CROWS + (L & 7);
        int gi = b * N + i;
        float4 f   = reinterpret_cast<const float4*>(inp)[gi];
        float4 csA = reinterpret_cast<float4*>(g_colA)[gi];
        reinterpret_cast<float4*>(g_colA)[gi] = make_float4(0, 0, 0, 0);
        float od1 = g_odout1[gi];
        float dp0 = DELTA + f.x;
        float s60 = f.y - od1 * dnn(f.y, dp0);
        float s61 = f.z - od1 * dnn(f.z, dp0);
        float s62 = f.w - od1 * dnn(f.w, dp0);
        float pop1 = f.x - od1 + csA.x;
        s_st[L * 2 + 0] = make_float4(pop1, s60, s61, s62);
        s_st[L * 2 + 1] = make_float4(csA.y, csA.z, csA.w, 0.0f);
        g_pop1[gi] = pop1;
        g_sir6[gi * 2 + 0] = make_float4(s60, s61, s62, csA.y);
        g_sir6[gi * 2 + 1] = make_float4(csA.z, csA.w, 0.0f, 0.0f);
    }

#pragma unroll
    for (int s = 0; s < 2; s++) {
        load_chunk(bufs + s * CHUNK_FLOATS,
                   OD + (size_t)(slot + s * CTAS_PER_B) * CROWS * N, tid);
        cp_commit();
    }

    float acc[4][7] = {};
    for (int c = 0; c <= nch; c++) {
        if (c < nch) cp_wait<1>();
        __syncthreads();                                 // barrier1

        if (c < nch)
            rowsum_partials(bufs + (c % STAGES) * CHUNK_FLOATS, s_part, warp, lane);

        if (c > 0) {
            const float4* colp =
                reinterpret_cast<const float4*>(bufs + ((c - 1) % STAGES) * CHUNK_FLOATS) + tid;
            const float4* wrow = &s_w[((c - 1) & 1) * CROWS * 2];
#pragma unroll
            for (int r = 0; r < CROWS; r++) {
                float4 v  = colp[r * (N / 4)];
                float4 wa = wrow[r * 2 + 0];
                float4 wb = wrow[r * 2 + 1];
                float wk[7] = {wa.x, wa.y, wa.z, wa.w, wb.x, wb.y, wb.z};
#pragma unroll
                for (int k = 0; k < 7; k++) {
                    acc[0][k] = fmaf(v.x, wk[k], acc[0][k]);
                    acc[1][k] = fmaf(v.y, wk[k], acc[1][k]);
                    acc[2][k] = fmaf(v.z, wk[k], acc[2][k]);
                    acc[3][k] = fmaf(v.w, wk[k], acc[3][k]);
                }
            }
        }
        __syncthreads();                                 // barrier2

        if (c < nch && tid < CROWS) {
            float s = s_part[tid * 2 + 0] + s_part[tid * 2 + 1];
            float4 a  = s_st[(c * CROWS + tid) * 2 + 0];   // pop1, s6[0..2]
            float4 bb = s_st[(c * CROWS + tid) * 2 + 1];   // s6[3..5]
            int gi = b * N + (slot + c * CTAS_PER_B) * CROWS + tid;
            float ratio = dnn(a.x, DELTA + s);
            float sc = ratio < 1.0f ? ratio : 1.0f;
            g_odout2[gi] = sc * s;
            float dp1 = DELTA + a.x;
            s_w[((c & 1) * CROWS + tid) * 2 + 0] =
                make_float4(sc, sc * dnn(a.y, dp1), sc * dnn(a.z, dp1), sc * dnn(a.w, dp1));
            s_w[((c & 1) * CROWS + tid) * 2 + 1] =
                make_float4(sc * dnn(bb.x, dp1), sc * dnn(bb.y, dp1),
                            sc * dnn(bb.z, dp1), 0.0f);
        }

        if (c + 2 < nch)
            load_chunk(bufs + ((c + 2) % STAGES) * CHUNK_FLOATS,
                       OD + (size_t)(slot + (c + 2) * CTAS_PER_B) * CROWS * N, tid);
        cp_commit();
    }

#pragma unroll
    for (int cc = 0; cc < 4; cc++) {
        float* dst = g_colB + ((size_t)b * N + tid * 4 + cc) * 8;
#pragma unroll
        for (int k = 0; k < 7; k++) atomicAdd(dst + k, acc[cc][k]);
    }
}

// ---------------------------------------------------------------------------
// Final: fuses update<6> + GEMM(12->64) + relu + concat(pop). Re-zeros colB.
// ---------------------------------------------------------------------------
__global__ void __launch_bounds__(256) final_kernel(
    const float* __restrict__ kern,
    const float* __restrict__ bias,
    float* __restrict__ out)
{
    __shared__ float s_kern[12 * 64];
    const int tid = threadIdx.x;
    for (int t = tid; t < 12 * 64; t += 256) s_kern[t] = kern[t];
    __syncthreads();

    const int rowl = tid >> 6;
    const int c    = tid & 63;
    const int gi   = blockIdx.x * 4 + rowl;

    float pop1   = g_pop1[gi];
    float odout2 = g_odout2[gi];
    float4 a   = g_sir6[gi * 2 + 0];
    float4 b4  = g_sir6[gi * 2 + 1];
    float4 cb0 = reinterpret_cast<const float4*>(g_colB)[gi * 2 + 0];
    float4 cb1 = reinterpret_cast<const float4*>(g_colB)[gi * 2 + 1];

    float dp1 = DELTA + pop1;
    float s12[12];
    s12[0] = a.x  - odout2 * dnn(a.x,  dp1);
    s12[1] = a.y  - odout2 * dnn(a.y,  dp1);
    s12[2] = a.z  - odout2 * dnn(a.z,  dp1);
    s12[3] = a.w  - odout2 * dnn(a.w,  dp1);
    s12[4] = b4.x - odout2 * dnn(b4.x, dp1);
    s12[5] = b4.y - odout2 * dnn(b4.y, dp1);
    s12[6]  = cb0.y; s12[7]  = cb0.z; s12[8]  = cb0.w;
    s12[9]  = cb1.x; s12[10] = cb1.y; s12[11] = cb1.z;

    float acc = __ldg(&bias[c]);
#pragma unroll
    for (int f = 0; f < 12; f++)
        acc = fmaf(s12[f], s_kern[f * 64 + c], acc);
    acc = fmaxf(acc, 0.0f);

    float* orow = out + (size_t)gi * 65;
    orow[1 + c] = acc;
    if (c == 0) orow[0] = pop1 - odout2 + cb0.x;

    __syncthreads();                  // all colB reads done before re-zero
    if (c < 8) g_colB[gi * 8 + c] = 0.0f;
}

// ---------------------------------------------------------------------------
extern "C" void kernel_launch(void* const* d_in, const int* in_sizes, int n_in,
                              void* d_out, int out_size) {
    const float* inp  = (const float*)d_in[0];  // input_feature (8,2048,4)
    const float* od   = (const float*)d_in[1];  // OD_all (8,2,2048,2048)
    const float* kern = (const float*)d_in[2];  // kernel (12,64)
    const float* bias = (const float*)d_in[3];  // bias (64)
    float* out = (float*)d_out;                 // (8,2048,65)

    const int SMEM1 = STAGES * CHUNK_FLOATS * 4 + CROWS * 2 * 4
                    + 2 * CROWS * 16 + MAXCH * CROWS * 16;
    const int SMEM2 = STAGES * CHUNK_FLOATS * 4 + CROWS * 2 * 4
                    + 2 * CROWS * 2 * 16 + MAXCH * CROWS * 32;

    cudaFuncSetAttribute(pass1_kernel, cudaFuncAttributeMaxDynamicSharedMemorySize, SMEM1);
    cudaFuncSetAttribute(pass2_kernel, cudaFuncAttributeMaxDynamicSharedMemorySize, SMEM2);

    pass1_kernel<<<GRID, TPB, SMEM1>>>(inp, od);
    pass2_kernel<<<GRID, TPB, SMEM2>>>(inp, od);
    final_kernel<<<BN / 4, 256>>>(kern, bias, out);
}

// round 7
// speedup vs baseline: 1.2495x; 1.0057x over previous
#include <cuda_runtime.h>

#define B 8
#define N 2048
#define BN (B * N)
#define DELTA 1e-7f

#define TPB 768                         // 16 FMA warps + 8 producer/rowsum warps
#define NFMA 512                        // threads 0..511: FMA only
#define CROWS 8                         // rows per chunk: 8*2048*4B = 64KB
#define CHUNK_FLOATS (CROWS * N)        // 16384 floats
#define NCHUNKS (N / CROWS)             // 256 chunks per batch
#define CTAS_PER_B 18
#define GRID (B * CTAS_PER_B)           // 144 CTAs (1 per SM)
#define STAGES 3
#define MAXCH ((NCHUNKS + CTAS_PER_B - 1) / CTAS_PER_B)   // 15

// Persistent scratch (__device__ globals per allocation rules).
__device__ float  g_odout1[BN];
__device__ float  g_odout2[BN];
__device__ float  g_pop1[BN];
__device__ float4 g_sir6[BN * 2];   // SIR after iter 0 (6 floats in 2x float4)
__device__ float  g_colA[BN * 4];   // iter0 colsums [OD_in, SIR_in*3] (zeroed by pass2)
__device__ float  g_colB[BN * 8];   // iter1 colsums [OD_in, SIR_in*6, pad] (zeroed by final)

__device__ __forceinline__ float dnn(float n, float d) { return (d == 0.0f) ? 0.0f : n / d; }

__device__ __forceinline__ void cp_async16(float* s, const float* g) {
    unsigned sa = (unsigned)__cvta_generic_to_shared(s);
    asm volatile("cp.async.cg.shared.global [%0], [%1], 16;" :: "r"(sa), "l"(g));
}
__device__ __forceinline__ void cp_commit() { asm volatile("cp.async.commit_group;"); }
template<int Nw> __device__ __forceinline__ void cp_wait() {
    asm volatile("cp.async.wait_group %0;" :: "n"(Nw));
}
// Producer-warp-only barrier (256 threads). Required between cp_wait and
// reading data loaded by OTHER producer threads' cp.async.
__device__ __forceinline__ void producer_bar() {
    asm volatile("bar.sync 1, 256;" ::: "memory");
}

// Producer warps only: 256 threads x 16 x 16B = 64KB
__device__ __forceinline__ void load_chunk(float* dst, const float* src, int ltid) {
#pragma unroll
    for (int v = 0; v < CHUNK_FLOATS / 4 / 256; v++)   // 16 x 16B per thread
        cp_async16(dst + (size_t)(ltid + v * 256) * 4, src + (size_t)(ltid + v * 256) * 4);
}

// Full row sum by one warp (row r of the chunk buffer)
__device__ __forceinline__ float warp_rowsum(const float* buf, int r, int lane) {
    const float4* row = reinterpret_cast<const float4*>(buf + r * N) + lane;
    float s = 0.0f;
#pragma unroll
    for (int t = 0; t < 16; t++) {
        float4 v = row[t * 32];
        s += (v.x + v.y) + (v.z + v.w);
    }
#pragma unroll
    for (int o = 16; o; o >>= 1) s += __shfl_xor_sync(0xffffffffu, s, o);
    return s;
}

// ---------------------------------------------------------------------------
// Pass 1 (iteration 0, K=4). Warp-specialized: producer/rowsum || FMA.
// ---------------------------------------------------------------------------
__global__ void __launch_bounds__(TPB, 1) pass1_kernel(
    const float* __restrict__ inp, const float* __restrict__ od_all)
{
    extern __shared__ float sm[];
    float*  bufs = sm;                                             // [3][16384]
    float4* s_w  = reinterpret_cast<float4*>(sm + STAGES * CHUNK_FLOATS); // [2][CROWS]
    float4* s_st = s_w + 2 * CROWS;                                // [MAXCH*CROWS]

    const int b    = blockIdx.x / CTAS_PER_B;
    const int slot = blockIdx.x % CTAS_PER_B;
    const int tid  = threadIdx.x;
    const int warp = tid >> 5, lane = tid & 31;
    const bool is_fma  = (tid < NFMA);
    const int  ltid    = tid - NFMA;          // producer-local tid (0..255)
    const float* OD = od_all + (size_t)(b * 2) * N * N;
    const int nch = (NCHUNKS - 1 - slot) / CTAS_PER_B + 1;   // 14 or 15

    // One-time prefetch of per-row input features (all threads)
    for (int L = tid; L < nch * CROWS; L += TPB) {
        int i = (slot + (L >> 3) * CTAS_PER_B) * CROWS + (L & 7);
        s_st[L] = reinterpret_cast<const float4*>(inp)[b * N + i];
    }
    if (!is_fma) {
#pragma unroll
        for (int s = 0; s < 2; s++) {
            load_chunk(bufs + s * CHUNK_FLOATS,
                       OD + (size_t)(slot + s * CTAS_PER_B) * CROWS * N, ltid);
            cp_commit();
        }
    }
    __syncthreads();

    float acc[4][4] = {};
    for (int c = 0; c <= nch; c++) {
        if (is_fma) {
            if (c > 0) {
                const float4* colp =
                    reinterpret_cast<const float4*>(bufs + ((c - 1) % STAGES) * CHUNK_FLOATS) + tid;
                const float4* wrow = &s_w[((c - 1) & 1) * CROWS];
#pragma unroll
                for (int r = 0; r < CROWS; r++) {
                    float4 v = colp[r * (N / 4)];
                    float4 w = wrow[r];
                    float wk[4] = {w.x, w.y, w.z, w.w};
#pragma unroll
                    for (int k = 0; k < 4; k++) {
                        acc[0][k] = fmaf(v.x, wk[k], acc[0][k]);
                        acc[1][k] = fmaf(v.y, wk[k], acc[1][k]);
                        acc[2][k] = fmaf(v.z, wk[k], acc[2][k]);
                        acc[3][k] = fmaf(v.w, wk[k], acc[3][k]);
                    }
                }
            }
        } else {
            if (c < nch) {
                cp_wait<1>();      // my own groups for chunk c retired
                producer_bar();    // ALL producers' chunk-c writes visible
                const int r = warp - 16;           // one warp per row
                float s = warp_rowsum(bufs + (c % STAGES) * CHUNK_FLOATS, r, lane);
                if (lane == 0) {
                    float4 f = s_st[c * CROWS + r];
                    int gi = b * N + (slot + c * CTAS_PER_B) * CROWS + r;
                    float ratio = dnn(f.x, DELTA + s);
                    float sc = ratio < 1.0f ? ratio : 1.0f;
                    g_odout1[gi] = sc * s;
                    float dp = DELTA + f.x;
                    s_w[(c & 1) * CROWS + r] =
                        make_float4(sc, sc * dnn(f.y, dp), sc * dnn(f.z, dp), sc * dnn(f.w, dp));
                }
            }
        }
        __syncthreads();   // publishes s_w(c) + chunk c data; retires buffer (c-1)%3

        if (!is_fma) {
            if (c + 2 < nch)
                load_chunk(bufs + ((c + 2) % STAGES) * CHUNK_FLOATS,
                           OD + (size_t)(slot + (c + 2) * CTAS_PER_B) * CROWS * N, ltid);
            cp_commit();   // exactly one group per iteration keeps wait<1> aligned
        }
    }

    if (is_fma) {
#pragma unroll
        for (int cc = 0; cc < 4; cc++) {
            float* dst = g_colA + ((size_t)b * N + tid * 4 + cc) * 4;
#pragma unroll
            for (int k = 0; k < 4; k++) atomicAdd(dst + k, acc[cc][k]);
        }
    }
}

// ---------------------------------------------------------------------------
// Pass 2 (iteration 1, K=7). Fuses update<3> in the state prefetch.
// ---------------------------------------------------------------------------
__global__ void __launch_bounds__(TPB, 1) pass2_kernel(
    const float* __restrict__ inp, const float* __restrict__ od_all)
{
    extern __shared__ float sm[];
    float*  bufs = sm;                                             // [3][16384]
    float4* s_w  = reinterpret_cast<float4*>(sm + STAGES * CHUNK_FLOATS); // [2][CROWS][2]
    float4* s_st = s_w + 2 * CROWS * 2;                            // [MAXCH*CROWS*2]

    const int b    = blockIdx.x / CTAS_PER_B;
    const int slot = blockIdx.x % CTAS_PER_B;
    const int tid  = threadIdx.x;
    const int warp = tid >> 5, lane = tid & 31;
    const bool is_fma = (tid < NFMA);
    const int  ltid   = tid - NFMA;
    const float* OD = od_all + (size_t)(b * 2 + 1) * N * N;
    const int nch = (NCHUNKS - 1 - slot) / CTAS_PER_B + 1;

    // One-time prefetch + fused iter-0 state update; re-zero colA for replay
    for (int L = tid; L < nch * CROWS; L += TPB) {
        int i  = (slot + (L >> 3) * CTAS_PER_B) * CROWS + (L & 7);
        int gi = b * N + i;
        float4 f   = reinterpret_cast<const float4*>(inp)[gi];
        float4 csA = reinterpret_cast<float4*>(g_colA)[gi];
        reinterpret_cast<float4*>(g_colA)[gi] = make_float4(0, 0, 0, 0);
        float od1 = g_odout1[gi];
        float dp0 = DELTA + f.x;
        float s60 = f.y - od1 * dnn(f.y, dp0);
        float s61 = f.z - od1 * dnn(f.z, dp0);
        float s62 = f.w - od1 * dnn(f.w, dp0);
        float pop1 = f.x - od1 + csA.x;
        s_st[L * 2 + 0] = make_float4(pop1, s60, s61, s62);
        s_st[L * 2 + 1] = make_float4(csA.y, csA.z, csA.w, 0.0f);
        g_pop1[gi] = pop1;
        g_sir6[gi * 2 + 0] = make_float4(s60, s61, s62, csA.y);
        g_sir6[gi * 2 + 1] = make_float4(csA.z, csA.w, 0.0f, 0.0f);
    }
    if (!is_fma) {
#pragma unroll
        for (int s = 0; s < 2; s++) {
            load_chunk(bufs + s * CHUNK_FLOATS,
                       OD + (size_t)(slot + s * CTAS_PER_B) * CROWS * N, ltid);
            cp_commit();
        }
    }
    __syncthreads();

    float acc[4][7] = {};
    for (int c = 0; c <= nch; c++) {
        if (is_fma) {
            if (c > 0) {
                const float4* colp =
                    reinterpret_cast<const float4*>(bufs + ((c - 1) % STAGES) * CHUNK_FLOATS) + tid;
                const float4* wrow = &s_w[((c - 1) & 1) * CROWS * 2];
#pragma unroll
                for (int r = 0; r < CROWS; r++) {
                    float4 v  = colp[r * (N / 4)];
                    float4 wa = wrow[r * 2 + 0];
                    float4 wb = wrow[r * 2 + 1];
                    float wk[7] = {wa.x, wa.y, wa.z, wa.w, wb.x, wb.y, wb.z};
#pragma unroll
                    for (int k = 0; k < 7; k++) {
                        acc[0][k] = fmaf(v.x, wk[k], acc[0][k]);
                        acc[1][k] = fmaf(v.y, wk[k], acc[1][k]);
                        acc[2][k] = fmaf(v.z, wk[k], acc[2][k]);
                        acc[3][k] = fmaf(v.w, wk[k], acc[3][k]);
                    }
                }
            }
        } else {
            if (c < nch) {
                cp_wait<1>();
                producer_bar();
                const int r = warp - 16;
                float s = warp_rowsum(bufs + (c % STAGES) * CHUNK_FLOATS, r, lane);
                if (lane == 0) {
                    float4 a  = s_st[(c * CROWS + r) * 2 + 0];   // pop1, s6[0..2]
                    float4 bb = s_st[(c * CROWS + r) * 2 + 1];   // s6[3..5]
                    int gi = b * N + (slot + c * CTAS_PER_B) * CROWS + r;
                    float ratio = dnn(a.x, DELTA + s);
                    float sc = ratio < 1.0f ? ratio : 1.0f;
                    g_odout2[gi] = sc * s;
                    float dp1 = DELTA + a.x;
                    s_w[((c & 1) * CROWS + r) * 2 + 0] =
                        make_float4(sc, sc * dnn(a.y, dp1), sc * dnn(a.z, dp1), sc * dnn(a.w, dp1));
                    s_w[((c & 1) * CROWS + r) * 2 + 1] =
                        make_float4(sc * dnn(bb.x, dp1), sc * dnn(bb.y, dp1),
                                    sc * dnn(bb.z, dp1), 0.0f);
                }
            }
        }
        __syncthreads();

        if (!is_fma) {
            if (c + 2 < nch)
                load_chunk(bufs + ((c + 2) % STAGES) * CHUNK_FLOATS,
                           OD + (size_t)(slot + (c + 2) * CTAS_PER_B) * CROWS * N, ltid);
            cp_commit();
        }
    }

    if (is_fma) {
#pragma unroll
        for (int cc = 0; cc < 4; cc++) {
            float* dst = g_colB + ((size_t)b * N + tid * 4 + cc) * 8;
#pragma unroll
            for (int k = 0; k < 7; k++) atomicAdd(dst + k, acc[cc][k]);
        }
    }
}

// ---------------------------------------------------------------------------
// Final: fuses update<6> + GEMM(12->64) + relu + concat(pop). Re-zeros colB.
// ---------------------------------------------------------------------------
__global__ void __launch_bounds__(256) final_kernel(
    const float* __restrict__ kern,
    const float* __restrict__ bias,
    float* __restrict__ out)
{
    __shared__ float s_kern[12 * 64];
    const int tid = threadIdx.x;
    for (int t = tid; t < 12 * 64; t += 256) s_kern[t] = kern[t];
    __syncthreads();

    const int rowl = tid >> 6;
    const int c    = tid & 63;
    const int gi   = blockIdx.x * 4 + rowl;

    float pop1   = g_pop1[gi];
    float odout2 = g_odout2[gi];
    float4 a   = g_sir6[gi * 2 + 0];
    float4 b4  = g_sir6[gi * 2 + 1];
    float4 cb0 = reinterpret_cast<const float4*>(g_colB)[gi * 2 + 0];
    float4 cb1 = reinterpret_cast<const float4*>(g_colB)[gi * 2 + 1];

    float dp1 = DELTA + pop1;
    float s12[12];
    s12[0] = a.x  - odout2 * dnn(a.x,  dp1);
    s12[1] = a.y  - odout2 * dnn(a.y,  dp1);
    s12[2] = a.z  - odout2 * dnn(a.z,  dp1);
    s12[3] = a.w  - odout2 * dnn(a.w,  dp1);
    s12[4] = b4.x - odout2 * dnn(b4.x, dp1);
    s12[5] = b4.y - odout2 * dnn(b4.y, dp1);
    s12[6]  = cb0.y; s12[7]  = cb0.z; s12[8]  = cb0.w;
    s12[9]  = cb1.x; s12[10] = cb1.y; s12[11] = cb1.z;

    float acc = __ldg(&bias[c]);
#pragma unroll
    for (int f = 0; f < 12; f++)
        acc = fmaf(s12[f], s_kern[f * 64 + c], acc);
    acc = fmaxf(acc, 0.0f);

    float* orow = out + (size_t)gi * 65;
    orow[1 + c] = acc;
    if (c == 0) orow[0] = pop1 - odout2 + cb0.x;

    __syncthreads();                  // all colB reads done before re-zero
    if (c < 8) g_colB[gi * 8 + c] = 0.0f;
}

// ---------------------------------------------------------------------------
extern "C" void kernel_launch(void* const* d_in, const int* in_sizes, int n_in,
                              void* d_out, int out_size) {
    const float* inp  = (const float*)d_in[0];  // input_feature (8,2048,4)
    const float* od   = (const float*)d_in[1];  // OD_all (8,2,2048,2048)
    const float* kern = (const float*)d_in[2];  // kernel (12,64)
    const float* bias = (const float*)d_in[3];  // bias (64)
    float* out = (float*)d_out;                 // (8,2048,65)

    const int SMEM1 = STAGES * CHUNK_FLOATS * 4
                    + 2 * CROWS * 16 + MAXCH * CROWS * 16;
    const int SMEM2 = STAGES * CHUNK_FLOATS * 4
                    + 2 * CROWS * 2 * 16 + MAXCH * CROWS * 32;

    cudaFuncSetAttribute(pass1_kernel, cudaFuncAttributeMaxDynamicSharedMemorySize, SMEM1);
    cudaFuncSetAttribute(pass2_kernel, cudaFuncAttributeMaxDynamicSharedMemorySize, SMEM2);

    pass1_kernel<<<GRID, TPB, SMEM1>>>(inp, od);
    pass2_kernel<<<GRID, TPB, SMEM2>>>(inp, od);
    final_kernel<<<BN / 4, 256>>>(kern, bias, out);
}

// round 8
// speedup vs baseline: 1.3183x; 1.0551x over previous
#include <cuda_runtime.h>

#define B 8
#define N 2048
#define BN (B * N)
#define DELTA 1e-7f

#define TPB 512
#define CROWS 8                         // rows per chunk: 8*2048*4B = 64KB
#define NCHUNKS (N / CROWS)             // 256 chunks per batch
#define CTAS_PER_B 18
#define GRID (B * CTAS_PER_B)           // 144 CTAs (1 per SM)
#define MAXCH ((NCHUNKS + CTAS_PER_B - 1) / CTAS_PER_B)   // 15

// Persistent scratch (__device__ globals per allocation rules).
__device__ float  g_odout1[BN];
__device__ float  g_odout2[BN];
__device__ float  g_pop1[BN];
__device__ float4 g_sir6[BN * 2];   // SIR after iter 0 (6 floats in 2x float4)
__device__ float  g_colA[BN * 4];   // iter0 colsums [OD_in, SIR_in*3] (zeroed by pass2)
__device__ float  g_colB[BN * 8];   // iter1 colsums [OD_in, SIR_in*6, pad] (zeroed by final)

__device__ __forceinline__ float dnn(float n, float d) { return (d == 0.0f) ? 0.0f : n / d; }

// ---------------------------------------------------------------------------
// Pass 1 (iteration 0, K=4). Register-resident chunks, single LDG pass.
// ---------------------------------------------------------------------------
__global__ void __launch_bounds__(TPB, 1) pass1_kernel(
    const float* __restrict__ inp, const float* __restrict__ od_all)
{
    __shared__ float  s_part[CROWS * TPB];   // 16KB per-thread row partials
    __shared__ float4 s_w[CROWS];            // weights for current chunk
    __shared__ float4 s_st[MAXCH * CROWS];   // prefetched input features

    const int b    = blockIdx.x / CTAS_PER_B;
    const int slot = blockIdx.x % CTAS_PER_B;
    const int tid  = threadIdx.x;
    const int warp = tid >> 5, lane = tid & 31;
    const float4* ODb = reinterpret_cast<const float4*>(od_all + (size_t)(b * 2) * N * N);
    const int nch = (NCHUNKS - 1 - slot) / CTAS_PER_B + 1;   // 14 or 15

    for (int L = tid; L < nch * CROWS; L += TPB) {
        int i = (slot + (L >> 3) * CTAS_PER_B) * CROWS + (L & 7);
        s_st[L] = reinterpret_cast<const float4*>(inp)[b * N + i];
    }
    __syncthreads();

    float4 dA[CROWS], dB[CROWS];
    {   // prologue: chunk 0 -> dA
        const float4* p = ODb + (size_t)slot * CROWS * (N / 4) + tid;
#pragma unroll
        for (int r = 0; r < CROWS; r++) dA[r] = p[r * (N / 4)];
    }

    float acc[4][4] = {};

    auto body = [&](float4 (&cur)[CROWS], float4 (&nxt)[CROWS], int c) {
        // prefetch chunk c+1 into the other register set (one chunk ~2500cyc ahead)
        if (c + 1 < nch) {
            const float4* p = ODb + (size_t)(slot + (c + 1) * CTAS_PER_B) * CROWS * (N / 4) + tid;
#pragma unroll
            for (int r = 0; r < CROWS; r++) nxt[r] = p[r * (N / 4)];
        }
        // per-thread row partials (4 columns each)
#pragma unroll
        for (int r = 0; r < CROWS; r++)
            s_part[r * TPB + tid] = (cur[r].x + cur[r].y) + (cur[r].z + cur[r].w);
        __syncthreads();

        // warp r (<8) reduces row r and computes weights
        if (warp < CROWS) {
            const float4* pp = reinterpret_cast<const float4*>(s_part + warp * TPB);
            float s = 0.0f;
#pragma unroll
            for (int k = 0; k < TPB / 128; k++) {
                float4 v = pp[lane + k * 32];
                s += (v.x + v.y) + (v.z + v.w);
            }
#pragma unroll
            for (int o = 16; o; o >>= 1) s += __shfl_xor_sync(0xffffffffu, s, o);
            if (lane == 0) {
                float4 f = s_st[c * CROWS + warp];
                int gi = b * N + (slot + c * CTAS_PER_B) * CROWS + warp;
                float ratio = f.x / (DELTA + s);              // DELTA+s > 0 always
                float sc = ratio < 1.0f ? ratio : 1.0f;
                g_odout1[gi] = sc * s;
                float inv = 1.0f / (DELTA + f.x);             // > 0 always
                s_w[warp] = make_float4(sc, sc * (f.y * inv),
                                        sc * (f.z * inv), sc * (f.w * inv));
            }
        }
        __syncthreads();

        // K=4 weighted accumulation straight from registers
#pragma unroll
        for (int r = 0; r < CROWS; r++) {
            float4 v = cur[r];
            float4 w = s_w[r];
            float wk[4] = {w.x, w.y, w.z, w.w};
#pragma unroll
            for (int k = 0; k < 4; k++) {
                acc[0][k] = fmaf(v.x, wk[k], acc[0][k]);
                acc[1][k] = fmaf(v.y, wk[k], acc[1][k]);
                acc[2][k] = fmaf(v.z, wk[k], acc[2][k]);
                acc[3][k] = fmaf(v.w, wk[k], acc[3][k]);
            }
        }
        // s_part/s_w(c+1) writes are separated from these reads by the next
        // iteration's barriers (writes happen before bar1(c+1); reads of (c)
        // finished before bar2(c)). Safe.
    };

    for (int c = 0; c < nch; c += 2) {
        body(dA, dB, c);
        if (c + 1 < nch) body(dB, dA, c + 1);
    }

#pragma unroll
    for (int cc = 0; cc < 4; cc++) {
        float* dst = g_colA + ((size_t)b * N + tid * 4 + cc) * 4;
#pragma unroll
        for (int k = 0; k < 4; k++) atomicAdd(dst + k, acc[cc][k]);
    }
}

// ---------------------------------------------------------------------------
// Pass 2 (iteration 1, K=7). Fuses update<3> in the state prefetch.
// ---------------------------------------------------------------------------
__global__ void __launch_bounds__(TPB, 1) pass2_kernel(
    const float* __restrict__ inp, const float* __restrict__ od_all)
{
    __shared__ float  s_part[CROWS * TPB];   // 16KB
    __shared__ float4 s_w[CROWS * 2];        // 7 weights per row (2 float4)
    __shared__ float4 s_st[MAXCH * CROWS * 2];

    const int b    = blockIdx.x / CTAS_PER_B;
    const int slot = blockIdx.x % CTAS_PER_B;
    const int tid  = threadIdx.x;
    const int warp = tid >> 5, lane = tid & 31;
    const float4* ODb = reinterpret_cast<const float4*>(od_all + (size_t)(b * 2 + 1) * N * N);
    const int nch = (NCHUNKS - 1 - slot) / CTAS_PER_B + 1;

    // One-time prefetch + fused iter-0 state update; re-zero colA for replay
    for (int L = tid; L < nch * CROWS; L += TPB) {
        int i  = (slot + (L >> 3) * CTAS_PER_B) * CROWS + (L & 7);
        int gi = b * N + i;
        float4 f   = reinterpret_cast<const float4*>(inp)[gi];
        float4 csA = reinterpret_cast<float4*>(g_colA)[gi];
        reinterpret_cast<float4*>(g_colA)[gi] = make_float4(0, 0, 0, 0);
        float od1 = g_odout1[gi];
        float inv0 = 1.0f / (DELTA + f.x);
        float s60 = f.y - od1 * (f.y * inv0);
        float s61 = f.z - od1 * (f.z * inv0);
        float s62 = f.w - od1 * (f.w * inv0);
        float pop1 = f.x - od1 + csA.x;
        s_st[L * 2 + 0] = make_float4(pop1, s60, s61, s62);
        s_st[L * 2 + 1] = make_float4(csA.y, csA.z, csA.w, 0.0f);
        g_pop1[gi] = pop1;
        g_sir6[gi * 2 + 0] = make_float4(s60, s61, s62, csA.y);
        g_sir6[gi * 2 + 1] = make_float4(csA.z, csA.w, 0.0f, 0.0f);
    }
    __syncthreads();

    float4 dA[CROWS], dB[CROWS];
    {
        const float4* p = ODb + (size_t)slot * CROWS * (N / 4) + tid;
#pragma unroll
        for (int r = 0; r < CROWS; r++) dA[r] = p[r * (N / 4)];
    }

    float acc[4][7] = {};

    auto body = [&](float4 (&cur)[CROWS], float4 (&nxt)[CROWS], int c) {
        if (c + 1 < nch) {
            const float4* p = ODb + (size_t)(slot + (c + 1) * CTAS_PER_B) * CROWS * (N / 4) + tid;
#pragma unroll
            for (int r = 0; r < CROWS; r++) nxt[r] = p[r * (N / 4)];
        }
#pragma unroll
        for (int r = 0; r < CROWS; r++)
            s_part[r * TPB + tid] = (cur[r].x + cur[r].y) + (cur[r].z + cur[r].w);
        __syncthreads();

        if (warp < CROWS) {
            const float4* pp = reinterpret_cast<const float4*>(s_part + warp * TPB);
            float s = 0.0f;
#pragma unroll
            for (int k = 0; k < TPB / 128; k++) {
                float4 v = pp[lane + k * 32];
                s += (v.x + v.y) + (v.z + v.w);
            }
#pragma unroll
            for (int o = 16; o; o >>= 1) s += __shfl_xor_sync(0xffffffffu, s, o);
            if (lane == 0) {
                float4 a  = s_st[(c * CROWS + warp) * 2 + 0];   // pop1, s6[0..2]
                float4 bb = s_st[(c * CROWS + warp) * 2 + 1];   // s6[3..5]
                int gi = b * N + (slot + c * CTAS_PER_B) * CROWS + warp;
                float ratio = a.x / (DELTA + s);
                float sc = ratio < 1.0f ? ratio : 1.0f;
                g_odout2[gi] = sc * s;
                float inv = 1.0f / (DELTA + a.x);
                s_w[warp * 2 + 0] = make_float4(sc, sc * (a.y * inv),
                                                sc * (a.z * inv), sc * (a.w * inv));
                s_w[warp * 2 + 1] = make_float4(sc * (bb.x * inv), sc * (bb.y * inv),
                                                sc * (bb.z * inv), 0.0f);
            }
        }
        __syncthreads();

#pragma unroll
        for (int r = 0; r < CROWS; r++) {
            float4 v  = cur[r];
            float4 wa = s_w[r * 2 + 0];
            float4 wb = s_w[r * 2 + 1];
            float wk[7] = {wa.x, wa.y, wa.z, wa.w, wb.x, wb.y, wb.z};
#pragma unroll
            for (int k = 0; k < 7; k++) {
                acc[0][k] = fmaf(v.x, wk[k], acc[0][k]);
                acc[1][k] = fmaf(v.y, wk[k], acc[1][k]);
                acc[2][k] = fmaf(v.z, wk[k], acc[2][k]);
                acc[3][k] = fmaf(v.w, wk[k], acc[3][k]);
            }
        }
    };

    for (int c = 0; c < nch; c += 2) {
        body(dA, dB, c);
        if (c + 1 < nch) body(dB, dA, c + 1);
    }

#pragma unroll
    for (int cc = 0; cc < 4; cc++) {
        float* dst = g_colB + ((size_t)b * N + tid * 4 + cc) * 8;
#pragma unroll
        for (int k = 0; k < 7; k++) atomicAdd(dst + k, acc[cc][k]);
    }
}

// ---------------------------------------------------------------------------
// Final: fuses update<6> + GEMM(12->64) + relu + concat(pop). Re-zeros colB.
// ---------------------------------------------------------------------------
__global__ void __launch_bounds__(256) final_kernel(
    const float* __restrict__ kern,
    const float* __restrict__ bias,
    float* __restrict__ out)
{
    __shared__ float s_kern[12 * 64];
    const int tid = threadIdx.x;
    for (int t = tid; t < 12 * 64; t += 256) s_kern[t] = kern[t];
    __syncthreads();

    const int rowl = tid >> 6;
    const int c    = tid & 63;
    const int gi   = blockIdx.x * 4 + rowl;

    float pop1   = g_pop1[gi];
    float odout2 = g_odout2[gi];
    float4 a   = g_sir6[gi * 2 + 0];
    float4 b4  = g_sir6[gi * 2 + 1];
    float4 cb0 = reinterpret_cast<const float4*>(g_colB)[gi * 2 + 0];
    float4 cb1 = reinterpret_cast<const float4*>(g_colB)[gi * 2 + 1];

    float dp1 = DELTA + pop1;
    float s12[12];
    s12[0] = a.x  - odout2 * dnn(a.x,  dp1);
    s12[1] = a.y  - odout2 * dnn(a.y,  dp1);
    s12[2] = a.z  - odout2 * dnn(a.z,  dp1);
    s12[3] = a.w  - odout2 * dnn(a.w,  dp1);
    s12[4] = b4.x - odout2 * dnn(b4.x, dp1);
    s12[5] = b4.y - odout2 * dnn(b4.y, dp1);
    s12[6]  = cb0.y; s12[7]  = cb0.z; s12[8]  = cb0.w;
    s12[9]  = cb1.x; s12[10] = cb1.y; s12[11] = cb1.z;

    float acc = __ldg(&bias[c]);
#pragma unroll
    for (int f = 0; f < 12; f++)
        acc = fmaf(s12[f], s_kern[f * 64 + c], acc);
    acc = fmaxf(acc, 0.0f);

    float* orow = out + (size_t)gi * 65;
    orow[1 + c] = acc;
    if (c == 0) orow[0] = pop1 - odout2 + cb0.x;

    __syncthreads();                  // all colB reads done before re-zero
    if (c < 8) g_colB[gi * 8 + c] = 0.0f;
}

// ---------------------------------------------------------------------------
extern "C" void kernel_launch(void* const* d_in, const int* in_sizes, int n_in,
                              void* d_out, int out_size) {
    const float* inp  = (const float*)d_in[0];  // input_feature (8,2048,4)
    const float* od   = (const float*)d_in[1];  // OD_all (8,2,2048,2048)
    const float* kern = (const float*)d_in[2];  // kernel (12,64)
    const float* bias = (const float*)d_in[3];  // bias (64)
    float* out = (float*)d_out;                 // (8,2048,65)

    pass1_kernel<<<GRID, TPB>>>(inp, od);
    pass2_kernel<<<GRID, TPB>>>(inp, od);
    final_kernel<<<BN / 4, 256>>>(kern, bias, out);
}